// round 13
// baseline (speedup 1.0000x reference)
#include <cuda_runtime.h>
#include <cuda_fp16.h>
#include <mma.h>
#include <cstdint>

using namespace nvcuda;

// Fixed problem shape: B=4, S=2048 -> M=8192, K=IN=4096, N=OUT=4096, group=32
#define IN_MAX  4096
#define OUT_MAX 4096
#define M_MAX   8192

// Static device scratch (allocation-free per harness rules)
__device__ __half g_X[(size_t)M_MAX * IN_MAX];     // x in fp16, [M][K]
__device__ __half g_WT[(size_t)OUT_MAX * IN_MAX];  // dequantized W^T, [N][K] K-major

// ============================================================================
// cp.async helpers
// ============================================================================
__device__ __forceinline__ uint32_t smem_to_u32(const void* p) {
    uint32_t a;
    asm("{ .reg .u64 t; cvta.to.shared.u64 t, %1; cvt.u32.u64 %0, t; }" : "=r"(a) : "l"(p));
    return a;
}
__device__ __forceinline__ void cp_async16(uint32_t dst, const void* src) {
    asm volatile("cp.async.cg.shared.global [%0], [%1], 16;" :: "r"(dst), "l"(src));
}
__device__ __forceinline__ void cp_async_commit() {
    asm volatile("cp.async.commit_group;" ::: "memory");
}
template <int N>
__device__ __forceinline__ void cp_async_wait() {
    asm volatile("cp.async.wait_group %0;" :: "n"(N) : "memory");
}

// ============================================================================
// Fused prep kernel (round-11 version): block-range dispatch
//   blocks [0, convBlocks):   x fp32 -> fp16  (512 thr, 8 floats/thread)
//   blocks [convBlocks, ...): dequant 4-bit -> fp16 W^T [N][K]
// ============================================================================
#define PREP_THREADS 512

__global__ void __launch_bounds__(PREP_THREADS)
prep_kernel(const float* __restrict__ x, int n8,
            const int* __restrict__ qweight,
            const int* __restrict__ qzeros,
            const int* __restrict__ qscales,
            const float* __restrict__ qscales_zeros,
            const float* __restrict__ qscales_scales,
            const int* __restrict__ g_idx,
            int K, int N, int convBlocks) {
    if ((int)blockIdx.x < convBlocks) {
        int i = blockIdx.x * PREP_THREADS + threadIdx.x;
        if (i < n8) {
            const float4* src = reinterpret_cast<const float4*>(x) + 2 * (size_t)i;
            float4 v0 = src[0];
            float4 v1 = src[1];
            __half2 h[4];
            h[0] = __floats2half2_rn(v0.x, v0.y);
            h[1] = __floats2half2_rn(v0.z, v0.w);
            h[2] = __floats2half2_rn(v1.x, v1.y);
            h[3] = __floats2half2_rn(v1.z, v1.w);
            reinterpret_cast<int4*>(g_X)[i] = *reinterpret_cast<int4*>(h);
        }
    } else {
        int idx = (blockIdx.x - convBlocks) * PREP_THREADS + threadIdx.x;
        int P = K >> 3;
        if (idx >= P * N) return;
        int p = idx / N;
        int j = idx - p * N;

        // 8 consecutive K rows (p*8..p*8+7) lie in one group (8 | 32)
        int g = g_idx[p * 8];
        int z = (int)(((unsigned)qzeros[g * (N >> 3) + (j >> 3)] >> ((j & 7) * 4)) & 15u) + 1;
        float sc = ((float)qscales[(size_t)g * N + j] - qscales_zeros[g]) * qscales_scales[g];

        unsigned w = (unsigned)qweight[idx];
        __half h[8];
#pragma unroll
        for (int r = 0; r < 8; r++) {
            int wn = (int)((w >> (4 * r)) & 15u);
            h[r] = __float2half_rn((float)(wn - z) * sc);
        }
        *reinterpret_cast<int4*>(&g_WT[(size_t)j * K + p * 8]) = *reinterpret_cast<int4*>(h);
    }
}

// ============================================================================
// GEMM: pipelined WMMA, CTA tile 256x128x64, 512 threads (16 warps, 4x4),
// warp tile 64x32 (4x2 frags, 128 regs -> exactly 64K regs/SM), 3-stage
// cp.async pipeline (166KB smem, 1 CTA/SM = 16 warps/SM).
// vs best-known 128x128/2-CTA: -25% cp.async issue, -25% L2 tile traffic.
// 144B row stride (conflict-free 8-row LDSM phases: banks {0,4,...,28}).
// ============================================================================
#define BM 256
#define BN 128
#define BK 64
#define GEMM_THREADS 512
#define STAGES 3
#define LDA (BK + 8)          // 72 halves = 144 bytes
#define LDB (BK + 8)

static constexpr int A_ST = BM * LDA * 2;          // 36864 B per stage
static constexpr int B_ST = BN * LDB * 2;          // 18432 B per stage
static constexpr int OFF_B = STAGES * A_ST;        // 110592
static constexpr int SMEM_DYN = OFF_B + STAGES * B_ST + 16;  // ~166KB

__device__ __forceinline__ void load_stage(uint32_t sbase, int stage,
                                           const __half* Abase, const __half* Bbase,
                                           int k0, int K, int tid, bool active) {
    if (active) {
        uint32_t aoff = sbase + stage * A_ST;
        uint32_t boff = sbase + OFF_B + stage * B_ST;
        // A: 256 rows x 8 chunks (16B) = 2048 -> 4/thread
#pragma unroll
        for (int c = 0; c < 4; c++) {
            int i = tid + c * GEMM_THREADS;
            int row = i >> 3;
            int cc = i & 7;
            cp_async16(aoff + row * (LDA * 2) + cc * 16,
                       (const char*)(Abase + (size_t)row * K + k0) + cc * 16);
        }
        // B: 128 rows x 8 chunks = 1024 -> 2/thread
#pragma unroll
        for (int c = 0; c < 2; c++) {
            int i = tid + c * GEMM_THREADS;
            int row = i >> 3;
            int cc = i & 7;
            cp_async16(boff + row * (LDB * 2) + cc * 16,
                       (const char*)(Bbase + (size_t)row * K + k0) + cc * 16);
        }
    }
    cp_async_commit();
}

typedef wmma::fragment<wmma::matrix_a, 16, 16, 16, __half, wmma::row_major> FragA;
typedef wmma::fragment<wmma::matrix_b, 16, 16, 16, __half, wmma::col_major> FragB;
typedef wmma::fragment<wmma::accumulator, 16, 16, 16, float> FragC;

__device__ __forceinline__ void load_frags(FragA af[4], FragB bf[2],
                                           const __half* As, const __half* Bs,
                                           int wm, int wn, int kk) {
#pragma unroll
    for (int i = 0; i < 4; i++)
        wmma::load_matrix_sync(af[i], As + (size_t)(wm * 64 + i * 16) * LDA + kk, LDA);
#pragma unroll
    for (int j = 0; j < 2; j++)
        wmma::load_matrix_sync(bf[j], Bs + (size_t)(wn * 32 + j * 16) * LDB + kk, LDB);
}

__global__ void __launch_bounds__(GEMM_THREADS, 1)
gemm_kernel(float* __restrict__ C, int M, int N, int K) {
    extern __shared__ char dsm[];
    uint32_t sbase = smem_to_u32(dsm);

    int tid  = threadIdx.x;
    int warp = tid >> 5;
    int wm   = warp & 3;      // 0..3 -> 64-row slab (of 256)
    int wn   = warp >> 2;     // 0..3 -> 32-col slab (of 128)

    int bm = blockIdx.y * BM;
    int bn = blockIdx.x * BN;

    const __half* Abase = &g_X[(size_t)bm * K];
    const __half* Bbase = &g_WT[(size_t)bn * K];

    FragC acc[4][2];
#pragma unroll
    for (int i = 0; i < 4; i++)
#pragma unroll
        for (int j = 0; j < 2; j++)
            wmma::fill_fragment(acc[i][j], 0.0f);

    int KT = K / BK;  // 64

#pragma unroll
    for (int s = 0; s < STAGES - 1; s++)
        load_stage(sbase, s, Abase, Bbase, s * BK, K, tid, true);

    FragA af[2][4];
    FragB bf[2][2];

    for (int kt = 0; kt < KT; kt++) {
        int st = kt % STAGES;
        cp_async_wait<STAGES - 2>();   // tile kt resident
        __syncthreads();               // all warps done reading the stage being refilled

        load_stage(sbase, (kt + STAGES - 1) % STAGES, Abase, Bbase,
                   (kt + STAGES - 1) * BK, K, tid, (kt + STAGES - 1) < KT);

        const __half* As = (const __half*)(dsm + st * A_ST);
        const __half* Bs = (const __half*)(dsm + OFF_B + st * B_ST);

        load_frags(af[0], bf[0], As, Bs, wm, wn, 0);
#pragma unroll
        for (int kk = 0; kk < BK / 16; kk++) {
            int cur = kk & 1;
            if (kk < BK / 16 - 1)
                load_frags(af[cur ^ 1], bf[cur ^ 1], As, Bs, wm, wn, (kk + 1) * 16);
#pragma unroll
            for (int i = 0; i < 4; i++)
#pragma unroll
                for (int j = 0; j < 2; j++)
                    wmma::mma_sync(acc[i][j], af[cur][i], bf[cur][j], acc[i][j]);
        }
    }

    // Epilogue: direct fp32 stores
#pragma unroll
    for (int i = 0; i < 4; i++)
#pragma unroll
        for (int j = 0; j < 2; j++) {
            float* dst = &C[(size_t)(bm + wm * 64 + i * 16) * N + bn + wn * 32 + j * 16];
            wmma::store_matrix_sync(dst, acc[i][j], N, wmma::mem_row_major);
        }
}

// ============================================================================
// Launch
// ============================================================================
extern "C" void kernel_launch(void* const* d_in, const int* in_sizes, int n_in,
                              void* d_out, int out_size) {
    const float* x   = (const float*)d_in[0];
    const int*   qw  = (const int*)d_in[1];
    const int*   qz  = (const int*)d_in[2];
    const int*   qs  = (const int*)d_in[3];
    const float* qsz = (const float*)d_in[4];
    const float* qss = (const float*)d_in[5];
    const int*   gix = (const int*)d_in[6];

    int K = in_sizes[6];                                  // IN = 4096
    int N = (int)(((long long)in_sizes[1] * 8) / K);      // OUT = 4096
    int M = in_sizes[0] / K;                              // 8192

    float* out = (float*)d_out;

    // Fused prep: convert (8 floats/thread) + dequant in one launch
    {
        int n8 = (M * K) / 8;
        int convBlocks = (n8 + PREP_THREADS - 1) / PREP_THREADS;
        int deqTotal = (K / 8) * N;
        int deqBlocks = (deqTotal + PREP_THREADS - 1) / PREP_THREADS;
        prep_kernel<<<convBlocks + deqBlocks, PREP_THREADS>>>(
            x, n8, qw, qz, qs, qsz, qss, gix, K, N, convBlocks);
    }
    // GEMM
    {
        cudaFuncSetAttribute(gemm_kernel,
                             cudaFuncAttributeMaxDynamicSharedMemorySize, SMEM_DYN);
        dim3 grid(N / BN, M / BM);   // (32, 32)
        gemm_kernel<<<grid, GEMM_THREADS, SMEM_DYN>>>(out, M, N, K);
    }
}

// round 15
// speedup vs baseline: 1.0695x; 1.0695x over previous
#include <cuda_runtime.h>
#include <cuda_fp16.h>
#include <mma.h>
#include <cstdint>

using namespace nvcuda;

// Fixed problem shape: B=4, S=2048 -> M=8192, K=IN=4096, N=OUT=4096, group=32
#define IN_MAX  4096
#define OUT_MAX 4096
#define M_MAX   8192

// Static device scratch (allocation-free per harness rules)
__device__ __half g_X[(size_t)M_MAX * IN_MAX];     // x in fp16, [M][K]
__device__ __half g_WT[(size_t)OUT_MAX * IN_MAX];  // dequantized W^T, [N][K] K-major

// ============================================================================
// cp.async helpers
// ============================================================================
__device__ __forceinline__ uint32_t smem_to_u32(const void* p) {
    uint32_t a;
    asm("{ .reg .u64 t; cvta.to.shared.u64 t, %1; cvt.u32.u64 %0, t; }" : "=r"(a) : "l"(p));
    return a;
}
__device__ __forceinline__ void cp_async16(uint32_t dst, const void* src) {
    asm volatile("cp.async.cg.shared.global [%0], [%1], 16;" :: "r"(dst), "l"(src));
}
__device__ __forceinline__ void cp_async_commit() {
    asm volatile("cp.async.commit_group;" ::: "memory");
}
template <int N>
__device__ __forceinline__ void cp_async_wait() {
    asm volatile("cp.async.wait_group %0;" :: "n"(N) : "memory");
}

// ============================================================================
// Fused prep kernel: block-range dispatch
//   blocks [0, convBlocks):   x fp32 -> fp16  (512 thr, 8 floats/thread)
//   blocks [convBlocks, ...): dequant 4-bit -> fp16 W^T [N][K]
// ============================================================================
#define PREP_THREADS 512

__global__ void __launch_bounds__(PREP_THREADS)
prep_kernel(const float* __restrict__ x, int n8,
            const int* __restrict__ qweight,
            const int* __restrict__ qzeros,
            const int* __restrict__ qscales,
            const float* __restrict__ qscales_zeros,
            const float* __restrict__ qscales_scales,
            const int* __restrict__ g_idx,
            int K, int N, int convBlocks) {
    if ((int)blockIdx.x < convBlocks) {
        int i = blockIdx.x * PREP_THREADS + threadIdx.x;
        if (i < n8) {
            const float4* src = reinterpret_cast<const float4*>(x) + 2 * (size_t)i;
            float4 v0 = src[0];
            float4 v1 = src[1];
            __half2 h[4];
            h[0] = __floats2half2_rn(v0.x, v0.y);
            h[1] = __floats2half2_rn(v0.z, v0.w);
            h[2] = __floats2half2_rn(v1.x, v1.y);
            h[3] = __floats2half2_rn(v1.z, v1.w);
            reinterpret_cast<int4*>(g_X)[i] = *reinterpret_cast<int4*>(h);
        }
    } else {
        int idx = (blockIdx.x - convBlocks) * PREP_THREADS + threadIdx.x;
        int P = K >> 3;
        if (idx >= P * N) return;
        int p = idx / N;
        int j = idx - p * N;

        // 8 consecutive K rows (p*8..p*8+7) lie in one group (8 | 32)
        int g = g_idx[p * 8];
        int z = (int)(((unsigned)qzeros[g * (N >> 3) + (j >> 3)] >> ((j & 7) * 4)) & 15u) + 1;
        float sc = ((float)qscales[(size_t)g * N + j] - qscales_zeros[g]) * qscales_scales[g];

        unsigned w = (unsigned)qweight[idx];
        __half h[8];
#pragma unroll
        for (int r = 0; r < 8; r++) {
            int wn = (int)((w >> (4 * r)) & 15u);
            h[r] = __float2half_rn((float)(wn - z) * sc);
        }
        *reinterpret_cast<int4*>(&g_WT[(size_t)j * K + p * 8]) = *reinterpret_cast<int4*>(h);
    }
}

// ============================================================================
// GEMM (measured optimum, round 11): pipelined WMMA, 2 CTAs/SM
//   C[M][N] = g_X[M][K] * g_WT[N][K]^T,  fp16 in / fp32 accum
// CTA tile 128x128x64, 8 warps (2x4), warp tile 64x32 (4x2 frags),
// 3-stage cp.async pipeline (108KB smem -> 2 CTAs/SM, 16 warps/SM; the two
// independent CTAs desynchronize barriers and keep the tensor pipe fed),
// 144B row stride (conflict-free 8-row LDSM phases: banks {0,4,...,28}).
// ============================================================================
#define BM 128
#define BN 128
#define BK 64
#define STAGES 3
#define LDA (BK + 8)          // 72 halves = 144 bytes
#define LDB (BK + 8)

static constexpr int A_ST = BM * LDA * 2;          // 18432 B per stage
static constexpr int B_ST = BN * LDB * 2;          // 18432 B per stage
static constexpr int OFF_B = STAGES * A_ST;        // 55296
static constexpr int SMEM_DYN = OFF_B + STAGES * B_ST + 16;  // ~108KB

__device__ __forceinline__ void load_stage(uint32_t sbase, int stage,
                                           const __half* Abase, const __half* Bbase,
                                           int k0, int K, int tid, bool active) {
    if (active) {
        uint32_t aoff = sbase + stage * A_ST;
        uint32_t boff = sbase + OFF_B + stage * B_ST;
        // A: 128 rows x 8 chunks (16B) = 1024 -> 4/thread
#pragma unroll
        for (int c = 0; c < 4; c++) {
            int i = tid + c * 256;
            int row = i >> 3;
            int cc = i & 7;
            cp_async16(aoff + row * (LDA * 2) + cc * 16,
                       (const char*)(Abase + (size_t)row * K + k0) + cc * 16);
        }
        // B: 128 rows x 8 chunks = 1024 -> 4/thread
#pragma unroll
        for (int c = 0; c < 4; c++) {
            int i = tid + c * 256;
            int row = i >> 3;
            int cc = i & 7;
            cp_async16(boff + row * (LDB * 2) + cc * 16,
                       (const char*)(Bbase + (size_t)row * K + k0) + cc * 16);
        }
    }
    cp_async_commit();
}

typedef wmma::fragment<wmma::matrix_a, 16, 16, 16, __half, wmma::row_major> FragA;
typedef wmma::fragment<wmma::matrix_b, 16, 16, 16, __half, wmma::col_major> FragB;
typedef wmma::fragment<wmma::accumulator, 16, 16, 16, float> FragC;

__device__ __forceinline__ void load_frags(FragA af[4], FragB bf[2],
                                           const __half* As, const __half* Bs,
                                           int wm, int wn, int kk) {
#pragma unroll
    for (int i = 0; i < 4; i++)
        wmma::load_matrix_sync(af[i], As + (size_t)(wm * 64 + i * 16) * LDA + kk, LDA);
#pragma unroll
    for (int j = 0; j < 2; j++)
        wmma::load_matrix_sync(bf[j], Bs + (size_t)(wn * 32 + j * 16) * LDB + kk, LDB);
}

__global__ void __launch_bounds__(256, 2)
gemm_kernel(float* __restrict__ C, int M, int N, int K) {
    extern __shared__ char dsm[];
    uint32_t sbase = smem_to_u32(dsm);

    int tid  = threadIdx.x;
    int warp = tid >> 5;
    int wm   = warp & 1;      // 0..1 -> 64-row slab
    int wn   = warp >> 1;     // 0..3 -> 32-col slab

    int bm = blockIdx.y * BM;
    int bn = blockIdx.x * BN;

    const __half* Abase = &g_X[(size_t)bm * K];
    const __half* Bbase = &g_WT[(size_t)bn * K];

    FragC acc[4][2];
#pragma unroll
    for (int i = 0; i < 4; i++)
#pragma unroll
        for (int j = 0; j < 2; j++)
            wmma::fill_fragment(acc[i][j], 0.0f);

    int KT = K / BK;  // 64

#pragma unroll
    for (int s = 0; s < STAGES - 1; s++)
        load_stage(sbase, s, Abase, Bbase, s * BK, K, tid, true);

    FragA af[2][4];
    FragB bf[2][2];

    for (int kt = 0; kt < KT; kt++) {
        int st = kt % STAGES;
        cp_async_wait<STAGES - 2>();   // tile kt resident
        __syncthreads();               // all warps done reading the stage being refilled

        load_stage(sbase, (kt + STAGES - 1) % STAGES, Abase, Bbase,
                   (kt + STAGES - 1) * BK, K, tid, (kt + STAGES - 1) < KT);

        const __half* As = (const __half*)(dsm + st * A_ST);
        const __half* Bs = (const __half*)(dsm + OFF_B + st * B_ST);

        load_frags(af[0], bf[0], As, Bs, wm, wn, 0);
#pragma unroll
        for (int kk = 0; kk < BK / 16; kk++) {
            int cur = kk & 1;
            if (kk < BK / 16 - 1)
                load_frags(af[cur ^ 1], bf[cur ^ 1], As, Bs, wm, wn, (kk + 1) * 16);
#pragma unroll
            for (int i = 0; i < 4; i++)
#pragma unroll
                for (int j = 0; j < 2; j++)
                    wmma::mma_sync(acc[i][j], af[cur][i], bf[cur][j], acc[i][j]);
        }
    }

    // Epilogue: direct fp32 stores
#pragma unroll
    for (int i = 0; i < 4; i++)
#pragma unroll
        for (int j = 0; j < 2; j++) {
            float* dst = &C[(size_t)(bm + wm * 64 + i * 16) * N + bn + wn * 32 + j * 16];
            wmma::store_matrix_sync(dst, acc[i][j], N, wmma::mem_row_major);
        }
}

// ============================================================================
// Launch
// ============================================================================
extern "C" void kernel_launch(void* const* d_in, const int* in_sizes, int n_in,
                              void* d_out, int out_size) {
    const float* x   = (const float*)d_in[0];
    const int*   qw  = (const int*)d_in[1];
    const int*   qz  = (const int*)d_in[2];
    const int*   qs  = (const int*)d_in[3];
    const float* qsz = (const float*)d_in[4];
    const float* qss = (const float*)d_in[5];
    const int*   gix = (const int*)d_in[6];

    int K = in_sizes[6];                                  // IN = 4096
    int N = (int)(((long long)in_sizes[1] * 8) / K);      // OUT = 4096
    int M = in_sizes[0] / K;                              // 8192

    float* out = (float*)d_out;

    // Fused prep: convert (8 floats/thread) + dequant in one launch
    {
        int n8 = (M * K) / 8;
        int convBlocks = (n8 + PREP_THREADS - 1) / PREP_THREADS;
        int deqTotal = (K / 8) * N;
        int deqBlocks = (deqTotal + PREP_THREADS - 1) / PREP_THREADS;
        prep_kernel<<<convBlocks + deqBlocks, PREP_THREADS>>>(
            x, n8, qw, qz, qs, qsz, qss, gix, K, N, convBlocks);
    }
    // GEMM
    {
        cudaFuncSetAttribute(gemm_kernel,
                             cudaFuncAttributeMaxDynamicSharedMemorySize, SMEM_DYN);
        dim3 grid(N / BN, M / BM);   // (32, 64)
        gemm_kernel<<<grid, 256, SMEM_DYN>>>(out, M, N, K);
    }
}